// round 6
// baseline (speedup 1.0000x reference)
#include <cuda_runtime.h>
#include <cuda_fp16.h>
#include <math.h>
#include <stdint.h>

#define TWO_B 32768
#define B_HALF 16384
#define DIM 256
#define KC 1024
#define BM 128
#define BN 128

// ---------------- device scratch (static, no allocation) ----------------
__device__ __align__(16) __half g_zh[(size_t)TWO_B * DIM];
__device__ __align__(16) __half g_ph[(size_t)TWO_B * DIM];
__device__ __align__(16) __half g_ch[(size_t)KC * DIM];
__device__ float g_nz[TWO_B];
__device__ float g_np[TWO_B];
__device__ float g_nc[KC];
__device__ __align__(16) __half g_tz[(size_t)TWO_B * KC];   // t stored fp16 (64 MB)
__device__ __align__(16) __half g_tp[(size_t)TWO_B * KC];
__device__ float g_cs[4 * KC];
__device__ float g_lcs[4 * KC];
__device__ double g_loss;

// ---------------- PTX helpers ----------------
__device__ __forceinline__ uint32_t smem_u32(const void* p) {
    uint32_t a;
    asm("{ .reg .u64 t; cvta.to.shared.u64 t, %1; cvt.u32.u64 %0, t; }" : "=r"(a) : "l"(p));
    return a;
}
#define CP_ASYNC16(dst, src) \
    asm volatile("cp.async.cg.shared.global [%0], [%1], 16;" :: "r"(dst), "l"(src) : "memory")
#define CP_COMMIT() asm volatile("cp.async.commit_group;" ::: "memory")
#define CP_WAIT(n)  asm volatile("cp.async.wait_group %0;" :: "n"(n) : "memory")
#define LDSM_X4(r0, r1, r2, r3, addr) \
    asm volatile("ldmatrix.sync.aligned.m8n8.x4.shared.b16 {%0,%1,%2,%3}, [%4];" \
                 : "=r"(r0), "=r"(r1), "=r"(r2), "=r"(r3) : "r"(addr))

// fp16-accumulate HMMA with C = 0; D returned as 2x f16x2 regs
__device__ __forceinline__ void mma_f16acc0(uint32_t* d, const uint32_t* a, const uint32_t* b) {
    asm volatile(
        "mma.sync.aligned.m16n8k16.row.col.f16.f16.f16.f16 "
        "{%0,%1}, {%2,%3,%4,%5}, {%6,%7}, {%8,%9};"
        : "=r"(d[0]), "=r"(d[1])
        : "r"(a[0]), "r"(a[1]), "r"(a[2]), "r"(a[3]), "r"(b[0]), "r"(b[1]),
          "r"(0u), "r"(0u));
}

__device__ __forceinline__ float distf(float sq) {
    return 20.0f * sqrtf(fmaxf(sq, 1e-12f));
}

// ---------------- small kernels ----------------
__global__ void zero_kernel() {
    int i = blockIdx.x * blockDim.x + threadIdx.x;
    if (i < 4 * KC) g_cs[i] = 0.0f;
    if (i == 0) g_loss = 0.0;
}

__device__ __forceinline__ void norm_row(const float* __restrict__ src,
                                         __half* __restrict__ dst,
                                         float* __restrict__ nsq, int r, int lane) {
    const float4* s4 = reinterpret_cast<const float4*>(src + (size_t)r * DIM);
    float4 v0 = s4[lane * 2];
    float4 v1 = s4[lane * 2 + 1];
    float ss = v0.x * v0.x + v0.y * v0.y + v0.z * v0.z + v0.w * v0.w
             + v1.x * v1.x + v1.y * v1.y + v1.z * v1.z + v1.w * v1.w;
    #pragma unroll
    for (int o = 16; o > 0; o >>= 1)
        ss += __shfl_xor_sync(0xffffffffu, ss, o);
    float inv = 1.0f / fmaxf(sqrtf(ss), 1e-12f);
    __half2 h[4];
    h[0] = __floats2half2_rn(v0.x * inv, v0.y * inv);
    h[1] = __floats2half2_rn(v0.z * inv, v0.w * inv);
    h[2] = __floats2half2_rn(v1.x * inv, v1.y * inv);
    h[3] = __floats2half2_rn(v1.z * inv, v1.w * inv);
    *reinterpret_cast<uint4*>(dst + (size_t)r * DIM + lane * 8) = *reinterpret_cast<uint4*>(h);
    if (lane == 0) nsq[r] = ss * inv * inv;
}

__global__ __launch_bounds__(256) void normalize_c_kernel(const float* __restrict__ c) {
    int row = blockIdx.x * 8 + (threadIdx.x >> 5);
    norm_row(c, g_ch, g_nc, row, threadIdx.x & 31);
}

__global__ __launch_bounds__(256) void normalize_zp_kernel(const float* __restrict__ z,
                                                           const float* __restrict__ p) {
    int row = blockIdx.x * 8 + (threadIdx.x >> 5);
    int lane = threadIdx.x & 31;
    if (row < TWO_B) norm_row(z, g_zh, g_nz, row, lane);
    else             norm_row(p, g_ph, g_np, row - TWO_B, lane);
}

// ---------------- fp16 HMMA GEMM + fused distance/exp epilogue ----------------
// grid = (KC/BN, TWO_B/BM, 2), block = 256, dynamic smem
#define NS 4              // pipeline stages
#define NSTAGES_K 8       // 256 / 32
#define STAGE_B 10240     // 128 rows * 80 bytes
#define SMEM_TOTAL (2 * NS * STAGE_B + 512)

__global__ __launch_bounds__(256, 2) void gemm_dist_hmma() {
    extern __shared__ char dsm[];
    uint32_t sA = smem_u32(dsm);
    uint32_t sB = sA + NS * STAGE_B;
    float* colacc = reinterpret_cast<float*>(dsm + 2 * NS * STAGE_B);

    int tid = threadIdx.x;
    int lane = tid & 31;
    int wid = tid >> 5;
    int wm = wid >> 2;   // 0..1
    int wn = wid & 3;    // 0..3
    int q = lane & 3;
    int gr = lane >> 2;

    int which = blockIdx.z;
    int bm = blockIdx.y;
    int bn = blockIdx.x;

    const __half* Ag = (which ? g_ph : g_zh) + (size_t)(bm * BM) * DIM;
    const __half* Bg = g_ch + (size_t)(bn * BN) * DIM;
    const float* na = which ? g_np : g_nz;
    __half* T = which ? g_tp : g_tz;

    int ltile = tid >> 7;       // 0 = A, 1 = B
    int lrow = tid & 127;
    const __half* gsrc = (ltile ? Bg : Ag) + (size_t)lrow * DIM;
    uint32_t sdst = (ltile ? sB : sA) + lrow * 80;

    float acc[4][4][4];
    #pragma unroll
    for (int i = 0; i < 4; i++)
        #pragma unroll
        for (int j = 0; j < 4; j++)
            #pragma unroll
            for (int k = 0; k < 4; k++)
                acc[i][j][k] = 0.0f;

    // prologue: issue stages 0..NS-2
    #pragma unroll
    for (int ps = 0; ps < NS - 1; ps++) {
        uint32_t d = sdst + (ps & (NS - 1)) * STAGE_B;
        const __half* g = gsrc + ps * 32;
        #pragma unroll
        for (int c2 = 0; c2 < 4; c2++)
            CP_ASYNC16(d + c2 * 16, g + c2 * 8);
        CP_COMMIT();
    }

    #pragma unroll
    for (int s = 0; s < NSTAGES_K; s++) {
        CP_WAIT(NS - 2);        // stage s arrived
        __syncthreads();        // all warps done reading buf (s-1)&3

        if (s + NS - 1 < NSTAGES_K) {
            uint32_t d = sdst + ((s + NS - 1) & (NS - 1)) * STAGE_B;
            const __half* g = gsrc + (s + NS - 1) * 32;
            #pragma unroll
            for (int c2 = 0; c2 < 4; c2++)
                CP_ASYNC16(d + c2 * 16, g + c2 * 8);
        }
        CP_COMMIT();            // always commit (possibly empty group)

        int buf = s & (NS - 1);
        uint32_t aB = sA + buf * STAGE_B + (wm * 64 + (lane & 15)) * 80 + (lane >> 4) * 16;
        uint32_t bB = sB + buf * STAGE_B + (wn * 32 + (lane & 7) + (lane >> 4) * 8) * 80
                      + ((lane >> 3) & 1) * 16;
        #pragma unroll
        for (int k16 = 0; k16 < 2; k16++) {
            uint32_t a[4][4], b[2][4];
            #pragma unroll
            for (int mt = 0; mt < 4; mt++)
                LDSM_X4(a[mt][0], a[mt][1], a[mt][2], a[mt][3],
                        aB + mt * (16 * 80) + k16 * 32);
            #pragma unroll
            for (int j = 0; j < 2; j++)
                LDSM_X4(b[j][0], b[j][1], b[j][2], b[j][3],
                        bB + j * (16 * 80) + k16 * 32);
            #pragma unroll
            for (int mt = 0; mt < 4; mt++) {
                #pragma unroll
                for (int nt = 0; nt < 4; nt++) {
                    uint32_t d[2];
                    mma_f16acc0(d, a[mt], &b[nt >> 1][(nt & 1) * 2]);
                    float2 f0 = __half22float2(*reinterpret_cast<__half2*>(&d[0]));
                    float2 f1 = __half22float2(*reinterpret_cast<__half2*>(&d[1]));
                    acc[mt][nt][0] += f0.x;
                    acc[mt][nt][1] += f0.y;
                    acc[mt][nt][2] += f1.x;
                    acc[mt][nt][3] += f1.y;
                }
            }
        }
    }
    __syncthreads();

    // ---------------- epilogue ----------------
    if (tid < BN) colacc[tid] = 0.0f;
    __syncthreads();

    float nc0v[4], nc1v[4];
    #pragma unroll
    for (int nt = 0; nt < 4; nt++) {
        int c = bn * BN + wn * 32 + nt * 8 + 2 * q;
        nc0v[nt] = g_nc[c];
        nc1v[nt] = g_nc[c + 1];
    }

    float es0[4], es1[4];
    #pragma unroll
    for (int nt = 0; nt < 4; nt++) { es0[nt] = 0.f; es1[nt] = 0.f; }

    #pragma unroll
    for (int mt = 0; mt < 4; mt++) {
        int r = bm * BM + wm * 64 + mt * 16 + gr;
        float na0 = na[r], na1 = na[r + 8];
        #pragma unroll
        for (int nt = 0; nt < 4; nt++) {
            int c = bn * BN + wn * 32 + nt * 8 + 2 * q;
            float t00 = distf(na0 + nc0v[nt] - 2.0f * acc[mt][nt][0]);
            float t01 = distf(na0 + nc1v[nt] - 2.0f * acc[mt][nt][1]);
            float t10 = distf(na1 + nc0v[nt] - 2.0f * acc[mt][nt][2]);
            float t11 = distf(na1 + nc1v[nt] - 2.0f * acc[mt][nt][3]);
            *(__half2*)&T[(size_t)r * KC + c]       = __floats2half2_rn(t00, t01);
            *(__half2*)&T[(size_t)(r + 8) * KC + c] = __floats2half2_rn(t10, t11);
            es0[nt] += __expf(t00) + __expf(t10);
            es1[nt] += __expf(t01) + __expf(t11);
        }
    }

    #pragma unroll
    for (int nt = 0; nt < 4; nt++) {
        int cl = wn * 32 + nt * 8 + 2 * q;
        atomicAdd(&colacc[cl], es0[nt]);
        atomicAdd(&colacc[cl + 1], es1[nt]);
    }
    __syncthreads();

    int csbase = (which * 2 + (bm >> 7)) * KC;
    if (tid < BN)
        atomicAdd(&g_cs[csbase + bn * BN + tid], colacc[tid]);
}

// ---------------- tail kernels ----------------
__global__ void logcs_kernel() {
    int i = blockIdx.x * blockDim.x + threadIdx.x;
    if (i < 4 * KC) g_lcs[i] = logf(g_cs[i]);
}

__global__ __launch_bounds__(256) void final_kernel() {
    __shared__ float sm[32];
    int b = blockIdx.x;
    int t = threadIdx.x;
    int lane = t & 31;
    int wid = t >> 5;
    int k0 = t * 4;

    uint2 rz1 = *(const uint2*)(g_tz + (size_t)b * KC + k0);
    uint2 rz2 = *(const uint2*)(g_tz + (size_t)(b + B_HALF) * KC + k0);
    uint2 rp1 = *(const uint2*)(g_tp + (size_t)b * KC + k0);
    uint2 rp2 = *(const uint2*)(g_tp + (size_t)(b + B_HALF) * KC + k0);
    float4 l1 = *(const float4*)(g_lcs + k0);
    float4 l2 = *(const float4*)(g_lcs + KC + k0);
    float4 l3 = *(const float4*)(g_lcs + 2 * KC + k0);
    float4 l4 = *(const float4*)(g_lcs + 3 * KC + k0);

    float tz1[4], tz2[4], tp1[4], tp2[4];
    {
        float2 a, bb;
        a = __half22float2(*(__half2*)&rz1.x); bb = __half22float2(*(__half2*)&rz1.y);
        tz1[0] = a.x; tz1[1] = a.y; tz1[2] = bb.x; tz1[3] = bb.y;
        a = __half22float2(*(__half2*)&rz2.x); bb = __half22float2(*(__half2*)&rz2.y);
        tz2[0] = a.x; tz2[1] = a.y; tz2[2] = bb.x; tz2[3] = bb.y;
        a = __half22float2(*(__half2*)&rp1.x); bb = __half22float2(*(__half2*)&rp1.y);
        tp1[0] = a.x; tp1[1] = a.y; tp1[2] = bb.x; tp1[3] = bb.y;
        a = __half22float2(*(__half2*)&rp2.x); bb = __half22float2(*(__half2*)&rp2.y);
        tp2[0] = a.x; tp2[1] = a.y; tp2[2] = bb.x; tp2[3] = bb.y;
    }
    float lc1[4] = {l1.x, l1.y, l1.z, l1.w};
    float lc2[4] = {l2.x, l2.y, l2.z, l2.w};
    float lc3[4] = {l3.x, l3.y, l3.z, l3.w};
    float lc4[4] = {l4.x, l4.y, l4.z, l4.w};

    float az1[4], az2[4], lp[4];
    float az1s = 0.f, az2s = 0.f, ap1s = 0.f, ap2s = 0.f;
    #pragma unroll
    for (int j = 0; j < 4; j++) {
        float u1 = tz1[j] - lc1[j];
        float u2 = tz2[j] - lc2[j];
        float v1 = tp1[j] - lc3[j];
        float v2 = tp2[j] - lc4[j];
        az1[j] = __expf(u1); az1s += az1[j];
        az2[j] = __expf(u2); az2s += az2[j];
        ap1s += __expf(v1);
        ap2s += __expf(v2);
        lp[j] = v1 + v2;
    }

    #pragma unroll
    for (int o = 16; o > 0; o >>= 1) {
        az1s += __shfl_xor_sync(0xffffffffu, az1s, o);
        az2s += __shfl_xor_sync(0xffffffffu, az2s, o);
        ap1s += __shfl_xor_sync(0xffffffffu, ap1s, o);
        ap2s += __shfl_xor_sync(0xffffffffu, ap2s, o);
    }
    if (lane == 0) {
        sm[wid * 4 + 0] = az1s; sm[wid * 4 + 1] = az2s;
        sm[wid * 4 + 2] = ap1s; sm[wid * 4 + 3] = ap2s;
    }
    __syncthreads();
    if (t < 32) {
        float v = sm[t];
        v += __shfl_xor_sync(0xffffffffu, v, 4);
        v += __shfl_xor_sync(0xffffffffu, v, 8);
        v += __shfl_xor_sync(0xffffffffu, v, 16);
        if (t < 4) sm[t] = v;
    }
    __syncthreads();
    float rz1s = sm[0], rz2s = sm[1], rp1s = sm[2], rp2s = sm[3];

    float lr = logf(rp1s) + logf(rp2s);
    float irz1 = 1.0f / rz1s;
    float irz2 = 1.0f / rz2s;
    float dot = 0.f;
    #pragma unroll
    for (int j = 0; j < 4; j++)
        dot += (az1[j] * irz1 + az2[j] * irz2) * (lp[j] - lr);

    #pragma unroll
    for (int o = 16; o > 0; o >>= 1)
        dot += __shfl_xor_sync(0xffffffffu, dot, o);
    if (lane == 0) sm[8 + wid] = dot;
    __syncthreads();
    if (t < 32) {
        float v = (t < 8) ? sm[8 + t] : 0.f;
        v += __shfl_xor_sync(0xffffffffu, v, 1);
        v += __shfl_xor_sync(0xffffffffu, v, 2);
        v += __shfl_xor_sync(0xffffffffu, v, 4);
        if (t == 0)
            atomicAdd(&g_loss, -(double)v / (4.0 * (double)B_HALF));
    }
}

__global__ void finalize_kernel(float* out) {
    out[0] = (float)g_loss;
}

// ---------------- launch ----------------
extern "C" void kernel_launch(void* const* d_in, const int* in_sizes, int n_in,
                              void* d_out, int out_size) {
    const float* z = (const float*)d_in[0];
    const float* p = (const float*)d_in[1];
    const float* c = (const float*)d_in[2];
    float* out = (float*)d_out;

    cudaFuncSetAttribute(gemm_dist_hmma, cudaFuncAttributeMaxDynamicSharedMemorySize, SMEM_TOTAL);

    zero_kernel<<<16, 256>>>();
    normalize_c_kernel<<<KC / 8, 256>>>(c);
    normalize_zp_kernel<<<2 * TWO_B / 8, 256>>>(z, p);
    dim3 ggrid(KC / BN, TWO_B / BM, 2);
    gemm_dist_hmma<<<ggrid, 256, SMEM_TOTAL>>>();
    logcs_kernel<<<16, 256>>>();
    final_kernel<<<B_HALF, 256>>>();
    finalize_kernel<<<1, 1>>>(out);
}

// round 7
// speedup vs baseline: 1.0616x; 1.0616x over previous
#include <cuda_runtime.h>
#include <cuda_fp16.h>
#include <math.h>
#include <stdint.h>

#define TWO_B 32768
#define B_HALF 16384
#define DIM 256
#define KC 1024
#define BM 128
#define BN 128

// ---------------- device scratch (static, no allocation) ----------------
__device__ __align__(16) __half g_zh[(size_t)TWO_B * DIM];
__device__ __align__(16) __half g_ph[(size_t)TWO_B * DIM];
__device__ __align__(16) __half g_ch[(size_t)KC * DIM];
__device__ float g_nz[TWO_B];
__device__ float g_np[TWO_B];
__device__ float g_nc[KC];
__device__ __align__(16) __half g_tz[(size_t)TWO_B * KC];   // t stored fp16 (64 MB)
__device__ __align__(16) __half g_tp[(size_t)TWO_B * KC];
__device__ float g_cs[4 * KC];
__device__ float g_lcs[4 * KC];
__device__ double g_loss;

// ---------------- PTX helpers ----------------
__device__ __forceinline__ uint32_t smem_u32(const void* p) {
    uint32_t a;
    asm("{ .reg .u64 t; cvta.to.shared.u64 t, %1; cvt.u32.u64 %0, t; }" : "=r"(a) : "l"(p));
    return a;
}
#define CP_ASYNC16(dst, src) \
    asm volatile("cp.async.cg.shared.global [%0], [%1], 16;" :: "r"(dst), "l"(src) : "memory")
#define CP_COMMIT() asm volatile("cp.async.commit_group;" ::: "memory")
#define CP_WAIT(n)  asm volatile("cp.async.wait_group %0;" :: "n"(n) : "memory")
#define LDSM_X4(r0, r1, r2, r3, addr) \
    asm volatile("ldmatrix.sync.aligned.m8n8.x4.shared.b16 {%0,%1,%2,%3}, [%4];" \
                 : "=r"(r0), "=r"(r1), "=r"(r2), "=r"(r3) : "r"(addr))

__device__ __forceinline__ void mma_f16(float* c, const uint32_t* a, const uint32_t* b) {
    asm volatile(
        "mma.sync.aligned.m16n8k16.row.col.f32.f16.f16.f32 "
        "{%0,%1,%2,%3}, {%4,%5,%6,%7}, {%8,%9}, {%0,%1,%2,%3};"
        : "+f"(c[0]), "+f"(c[1]), "+f"(c[2]), "+f"(c[3])
        : "r"(a[0]), "r"(a[1]), "r"(a[2]), "r"(a[3]), "r"(b[0]), "r"(b[1]));
}

__device__ __forceinline__ float distf(float sq) {
    return 20.0f * sqrtf(fmaxf(sq, 1e-12f));
}

// ---------------- small kernels ----------------
__global__ void zero_kernel() {
    int i = blockIdx.x * blockDim.x + threadIdx.x;
    if (i < 4 * KC) g_cs[i] = 0.0f;
    if (i == 0) g_loss = 0.0;
}

__device__ __forceinline__ void norm_row(const float* __restrict__ src,
                                         __half* __restrict__ dst,
                                         float* __restrict__ nsq, int r, int lane) {
    const float4* s4 = reinterpret_cast<const float4*>(src + (size_t)r * DIM);
    float4 v0 = s4[lane * 2];
    float4 v1 = s4[lane * 2 + 1];
    float ss = v0.x * v0.x + v0.y * v0.y + v0.z * v0.z + v0.w * v0.w
             + v1.x * v1.x + v1.y * v1.y + v1.z * v1.z + v1.w * v1.w;
    #pragma unroll
    for (int o = 16; o > 0; o >>= 1)
        ss += __shfl_xor_sync(0xffffffffu, ss, o);
    float inv = 1.0f / fmaxf(sqrtf(ss), 1e-12f);
    __half2 h[4];
    h[0] = __floats2half2_rn(v0.x * inv, v0.y * inv);
    h[1] = __floats2half2_rn(v0.z * inv, v0.w * inv);
    h[2] = __floats2half2_rn(v1.x * inv, v1.y * inv);
    h[3] = __floats2half2_rn(v1.z * inv, v1.w * inv);
    *reinterpret_cast<uint4*>(dst + (size_t)r * DIM + lane * 8) = *reinterpret_cast<uint4*>(h);
    if (lane == 0) nsq[r] = ss * inv * inv;
}

__global__ __launch_bounds__(256) void normalize_c_kernel(const float* __restrict__ c) {
    int row = blockIdx.x * 8 + (threadIdx.x >> 5);
    norm_row(c, g_ch, g_nc, row, threadIdx.x & 31);
}

__global__ __launch_bounds__(256) void normalize_zp_kernel(const float* __restrict__ z,
                                                           const float* __restrict__ p) {
    int row = blockIdx.x * 8 + (threadIdx.x >> 5);
    int lane = threadIdx.x & 31;
    if (row < TWO_B) norm_row(z, g_zh, g_nz, row, lane);
    else             norm_row(p, g_ph, g_np, row - TWO_B, lane);
}

// ---------------- fp16 HMMA GEMM + fused distance/exp epilogue ----------------
// grid = (KC/BN, TWO_B/BM, 2), block = 256, dynamic smem
// BK = 64 per stage, 2-stage double buffer: 4 barriers total in mainloop,
// 64 MMAs + 24 ldmatrix per warp between barriers.
#define NSTG 4            // K stages: 256 / 64
#define ROWB 144          // 64 halves payload + 8 pad = 144 bytes per row
#define STAGE_B (128 * ROWB)      // 18432 B per tile per stage
#define SMEM_TOTAL (4 * STAGE_B + 512)

__global__ __launch_bounds__(256, 2) void gemm_dist_hmma() {
    extern __shared__ char dsm[];
    uint32_t sA = smem_u32(dsm);                 // A: 2 stages
    uint32_t sB = sA + 2 * STAGE_B;              // B: 2 stages
    float* colacc = reinterpret_cast<float*>(dsm + 4 * STAGE_B);

    int tid = threadIdx.x;
    int lane = tid & 31;
    int wid = tid >> 5;
    int wm = wid >> 2;   // 0..1
    int wn = wid & 3;    // 0..3
    int q = lane & 3;
    int gr = lane >> 2;

    int which = blockIdx.z;
    int bm = blockIdx.y;
    int bn = blockIdx.x;

    const __half* Ag = (which ? g_ph : g_zh) + (size_t)(bm * BM) * DIM;
    const __half* Bg = g_ch + (size_t)(bn * BN) * DIM;
    const float* na = which ? g_np : g_nz;
    __half* T = which ? g_tp : g_tz;

    int ltile = tid >> 7;       // 0 = A, 1 = B
    int lrow = tid & 127;
    const __half* gsrc = (ltile ? Bg : Ag) + (size_t)lrow * DIM;
    uint32_t sdst = (ltile ? sB : sA) + lrow * ROWB;

    float acc[4][4][4];
    #pragma unroll
    for (int i = 0; i < 4; i++)
        #pragma unroll
        for (int j = 0; j < 4; j++)
            #pragma unroll
            for (int k = 0; k < 4; k++)
                acc[i][j][k] = 0.0f;

    // prologue: issue stage 0 into buf 0
    #pragma unroll
    for (int c2 = 0; c2 < 8; c2++)
        CP_ASYNC16(sdst + c2 * 16, gsrc + c2 * 8);
    CP_COMMIT();

    uint32_t aBase = sA + (wm * 64 + (lane & 15)) * ROWB + (lane >> 4) * 16;
    uint32_t bBase = sB + (wn * 32 + (lane & 7) + ((lane >> 4) << 3)) * ROWB
                     + ((lane >> 3) & 1) * 16;

    #pragma unroll
    for (int s = 0; s < NSTG; s++) {
        CP_WAIT(0);             // stage s data present
        __syncthreads();        // all warps done with buf (s+1)&1 (stage s-1)

        if (s + 1 < NSTG) {
            uint32_t d = sdst + ((s + 1) & 1) * STAGE_B;
            const __half* g = gsrc + (s + 1) * 64;
            #pragma unroll
            for (int c2 = 0; c2 < 8; c2++)
                CP_ASYNC16(d + c2 * 16, g + c2 * 8);
            CP_COMMIT();
        }

        uint32_t aB = aBase + (s & 1) * STAGE_B;
        uint32_t bB = bBase + (s & 1) * STAGE_B;
        #pragma unroll
        for (int k16 = 0; k16 < 4; k16++) {
            uint32_t a[4][4], b[2][4];
            #pragma unroll
            for (int mt = 0; mt < 4; mt++)
                LDSM_X4(a[mt][0], a[mt][1], a[mt][2], a[mt][3],
                        aB + mt * (16 * ROWB) + k16 * 32);
            #pragma unroll
            for (int j = 0; j < 2; j++)
                LDSM_X4(b[j][0], b[j][1], b[j][2], b[j][3],
                        bB + j * (16 * ROWB) + k16 * 32);
            #pragma unroll
            for (int mt = 0; mt < 4; mt++)
                #pragma unroll
                for (int nt = 0; nt < 4; nt++)
                    mma_f16(acc[mt][nt], a[mt], &b[nt >> 1][(nt & 1) * 2]);
        }
    }
    __syncthreads();

    // ---------------- epilogue ----------------
    if (tid < BN) colacc[tid] = 0.0f;
    __syncthreads();

    float nc0v[4], nc1v[4];
    #pragma unroll
    for (int nt = 0; nt < 4; nt++) {
        int c = bn * BN + wn * 32 + nt * 8 + 2 * q;
        nc0v[nt] = g_nc[c];
        nc1v[nt] = g_nc[c + 1];
    }

    float es0[4], es1[4];
    #pragma unroll
    for (int nt = 0; nt < 4; nt++) { es0[nt] = 0.f; es1[nt] = 0.f; }

    #pragma unroll
    for (int mt = 0; mt < 4; mt++) {
        int r = bm * BM + wm * 64 + mt * 16 + gr;
        float na0 = na[r], na1 = na[r + 8];
        #pragma unroll
        for (int nt = 0; nt < 4; nt++) {
            int c = bn * BN + wn * 32 + nt * 8 + 2 * q;
            float t00 = distf(na0 + nc0v[nt] - 2.0f * acc[mt][nt][0]);
            float t01 = distf(na0 + nc1v[nt] - 2.0f * acc[mt][nt][1]);
            float t10 = distf(na1 + nc0v[nt] - 2.0f * acc[mt][nt][2]);
            float t11 = distf(na1 + nc1v[nt] - 2.0f * acc[mt][nt][3]);
            *(__half2*)&T[(size_t)r * KC + c]       = __floats2half2_rn(t00, t01);
            *(__half2*)&T[(size_t)(r + 8) * KC + c] = __floats2half2_rn(t10, t11);
            es0[nt] += __expf(t00) + __expf(t10);
            es1[nt] += __expf(t01) + __expf(t11);
        }
    }

    #pragma unroll
    for (int nt = 0; nt < 4; nt++) {
        int cl = wn * 32 + nt * 8 + 2 * q;
        atomicAdd(&colacc[cl], es0[nt]);
        atomicAdd(&colacc[cl + 1], es1[nt]);
    }
    __syncthreads();

    int csbase = (which * 2 + (bm >> 7)) * KC;
    if (tid < BN)
        atomicAdd(&g_cs[csbase + bn * BN + tid], colacc[tid]);
}

// ---------------- tail kernels ----------------
__global__ void logcs_kernel() {
    int i = blockIdx.x * blockDim.x + threadIdx.x;
    if (i < 4 * KC) g_lcs[i] = logf(g_cs[i]);
}

__global__ __launch_bounds__(256) void final_kernel() {
    __shared__ float sm[32];
    int b = blockIdx.x;
    int t = threadIdx.x;
    int lane = t & 31;
    int wid = t >> 5;
    int k0 = t * 4;

    uint2 rz1 = *(const uint2*)(g_tz + (size_t)b * KC + k0);
    uint2 rz2 = *(const uint2*)(g_tz + (size_t)(b + B_HALF) * KC + k0);
    uint2 rp1 = *(const uint2*)(g_tp + (size_t)b * KC + k0);
    uint2 rp2 = *(const uint2*)(g_tp + (size_t)(b + B_HALF) * KC + k0);
    float4 l1 = *(const float4*)(g_lcs + k0);
    float4 l2 = *(const float4*)(g_lcs + KC + k0);
    float4 l3 = *(const float4*)(g_lcs + 2 * KC + k0);
    float4 l4 = *(const float4*)(g_lcs + 3 * KC + k0);

    float tz1[4], tz2[4], tp1[4], tp2[4];
    {
        float2 a, bb;
        a = __half22float2(*(__half2*)&rz1.x); bb = __half22float2(*(__half2*)&rz1.y);
        tz1[0] = a.x; tz1[1] = a.y; tz1[2] = bb.x; tz1[3] = bb.y;
        a = __half22float2(*(__half2*)&rz2.x); bb = __half22float2(*(__half2*)&rz2.y);
        tz2[0] = a.x; tz2[1] = a.y; tz2[2] = bb.x; tz2[3] = bb.y;
        a = __half22float2(*(__half2*)&rp1.x); bb = __half22float2(*(__half2*)&rp1.y);
        tp1[0] = a.x; tp1[1] = a.y; tp1[2] = bb.x; tp1[3] = bb.y;
        a = __half22float2(*(__half2*)&rp2.x); bb = __half22float2(*(__half2*)&rp2.y);
        tp2[0] = a.x; tp2[1] = a.y; tp2[2] = bb.x; tp2[3] = bb.y;
    }
    float lc1[4] = {l1.x, l1.y, l1.z, l1.w};
    float lc2[4] = {l2.x, l2.y, l2.z, l2.w};
    float lc3[4] = {l3.x, l3.y, l3.z, l3.w};
    float lc4[4] = {l4.x, l4.y, l4.z, l4.w};

    float az1[4], az2[4], lp[4];
    float az1s = 0.f, az2s = 0.f, ap1s = 0.f, ap2s = 0.f;
    #pragma unroll
    for (int j = 0; j < 4; j++) {
        float u1 = tz1[j] - lc1[j];
        float u2 = tz2[j] - lc2[j];
        float v1 = tp1[j] - lc3[j];
        float v2 = tp2[j] - lc4[j];
        az1[j] = __expf(u1); az1s += az1[j];
        az2[j] = __expf(u2); az2s += az2[j];
        ap1s += __expf(v1);
        ap2s += __expf(v2);
        lp[j] = v1 + v2;
    }

    #pragma unroll
    for (int o = 16; o > 0; o >>= 1) {
        az1s += __shfl_xor_sync(0xffffffffu, az1s, o);
        az2s += __shfl_xor_sync(0xffffffffu, az2s, o);
        ap1s += __shfl_xor_sync(0xffffffffu, ap1s, o);
        ap2s += __shfl_xor_sync(0xffffffffu, ap2s, o);
    }
    if (lane == 0) {
        sm[wid * 4 + 0] = az1s; sm[wid * 4 + 1] = az2s;
        sm[wid * 4 + 2] = ap1s; sm[wid * 4 + 3] = ap2s;
    }
    __syncthreads();
    if (t < 32) {
        float v = sm[t];
        v += __shfl_xor_sync(0xffffffffu, v, 4);
        v += __shfl_xor_sync(0xffffffffu, v, 8);
        v += __shfl_xor_sync(0xffffffffu, v, 16);
        if (t < 4) sm[t] = v;
    }
    __syncthreads();
    float rz1s = sm[0], rz2s = sm[1], rp1s = sm[2], rp2s = sm[3];

    float lr = logf(rp1s) + logf(rp2s);
    float irz1 = 1.0f / rz1s;
    float irz2 = 1.0f / rz2s;
    float dot = 0.f;
    #pragma unroll
    for (int j = 0; j < 4; j++)
        dot += (az1[j] * irz1 + az2[j] * irz2) * (lp[j] - lr);

    #pragma unroll
    for (int o = 16; o > 0; o >>= 1)
        dot += __shfl_xor_sync(0xffffffffu, dot, o);
    if (lane == 0) sm[8 + wid] = dot;
    __syncthreads();
    if (t < 32) {
        float v = (t < 8) ? sm[8 + t] : 0.f;
        v += __shfl_xor_sync(0xffffffffu, v, 1);
        v += __shfl_xor_sync(0xffffffffu, v, 2);
        v += __shfl_xor_sync(0xffffffffu, v, 4);
        if (t == 0)
            atomicAdd(&g_loss, -(double)v / (4.0 * (double)B_HALF));
    }
}

__global__ void finalize_kernel(float* out) {
    out[0] = (float)g_loss;
}

// ---------------- launch ----------------
extern "C" void kernel_launch(void* const* d_in, const int* in_sizes, int n_in,
                              void* d_out, int out_size) {
    const float* z = (const float*)d_in[0];
    const float* p = (const float*)d_in[1];
    const float* c = (const float*)d_in[2];
    float* out = (float*)d_out;

    cudaFuncSetAttribute(gemm_dist_hmma, cudaFuncAttributeMaxDynamicSharedMemorySize, SMEM_TOTAL);

    zero_kernel<<<16, 256>>>();
    normalize_c_kernel<<<KC / 8, 256>>>(c);
    normalize_zp_kernel<<<2 * TWO_B / 8, 256>>>(z, p);
    dim3 ggrid(KC / BN, TWO_B / BM, 2);
    gemm_dist_hmma<<<ggrid, 256, SMEM_TOTAL>>>();
    logcs_kernel<<<16, 256>>>();
    final_kernel<<<B_HALF, 256>>>();
    finalize_kernel<<<1, 1>>>(out);
}

// round 8
// speedup vs baseline: 1.0886x; 1.0254x over previous
#include <cuda_runtime.h>
#include <cuda_fp16.h>
#include <math.h>
#include <stdint.h>

#define TWO_B 32768
#define B_HALF 16384
#define DIM 256
#define KC 1024
#define BM 128
#define BN 128

// ---------------- device scratch (static, no allocation) ----------------
__device__ __align__(16) __half g_zh[(size_t)TWO_B * DIM];
__device__ __align__(16) __half g_ph[(size_t)TWO_B * DIM];
__device__ __align__(16) __half g_ch[(size_t)KC * DIM];
__device__ float g_nz[TWO_B];
__device__ float g_np[TWO_B];
__device__ float g_nc[KC];
__device__ __align__(16) __half g_tz[(size_t)TWO_B * KC];   // t stored fp16 (64 MB)
__device__ __align__(16) __half g_tp[(size_t)TWO_B * KC];
__device__ float g_cs[4 * KC];
__device__ float g_lcs[4 * KC];
__device__ double g_loss;

// ---------------- PTX helpers ----------------
__device__ __forceinline__ uint32_t smem_u32(const void* p) {
    uint32_t a;
    asm("{ .reg .u64 t; cvta.to.shared.u64 t, %1; cvt.u32.u64 %0, t; }" : "=r"(a) : "l"(p));
    return a;
}
#define CP_ASYNC16(dst, src) \
    asm volatile("cp.async.cg.shared.global [%0], [%1], 16;" :: "r"(dst), "l"(src) : "memory")
#define CP_COMMIT() asm volatile("cp.async.commit_group;" ::: "memory")
#define CP_WAIT(n)  asm volatile("cp.async.wait_group %0;" :: "n"(n) : "memory")
#define LDSM_X4(r0, r1, r2, r3, addr) \
    asm volatile("ldmatrix.sync.aligned.m8n8.x4.shared.b16 {%0,%1,%2,%3}, [%4];" \
                 : "=r"(r0), "=r"(r1), "=r"(r2), "=r"(r3) : "r"(addr))

__device__ __forceinline__ void mma_f16(float* c, const uint32_t* a, const uint32_t* b) {
    asm volatile(
        "mma.sync.aligned.m16n8k16.row.col.f32.f16.f16.f32 "
        "{%0,%1,%2,%3}, {%4,%5,%6,%7}, {%8,%9}, {%0,%1,%2,%3};"
        : "+f"(c[0]), "+f"(c[1]), "+f"(c[2]), "+f"(c[3])
        : "r"(a[0]), "r"(a[1]), "r"(a[2]), "r"(a[3]), "r"(b[0]), "r"(b[1]));
}

__device__ __forceinline__ float distf(float sq) {
    return 20.0f * sqrtf(fmaxf(sq, 1e-12f));
}

// ---------------- small kernels ----------------
__global__ void zero_kernel() {
    int i = blockIdx.x * blockDim.x + threadIdx.x;
    if (i < 4 * KC) g_cs[i] = 0.0f;
    if (i == 0) g_loss = 0.0;
}

__device__ __forceinline__ void norm_row(const float* __restrict__ src,
                                         __half* __restrict__ dst,
                                         float* __restrict__ nsq, int r, int lane) {
    const float4* s4 = reinterpret_cast<const float4*>(src + (size_t)r * DIM);
    float4 v0 = s4[lane * 2];
    float4 v1 = s4[lane * 2 + 1];
    float ss = v0.x * v0.x + v0.y * v0.y + v0.z * v0.z + v0.w * v0.w
             + v1.x * v1.x + v1.y * v1.y + v1.z * v1.z + v1.w * v1.w;
    #pragma unroll
    for (int o = 16; o > 0; o >>= 1)
        ss += __shfl_xor_sync(0xffffffffu, ss, o);
    float inv = 1.0f / fmaxf(sqrtf(ss), 1e-12f);
    __half2 h[4];
    h[0] = __floats2half2_rn(v0.x * inv, v0.y * inv);
    h[1] = __floats2half2_rn(v0.z * inv, v0.w * inv);
    h[2] = __floats2half2_rn(v1.x * inv, v1.y * inv);
    h[3] = __floats2half2_rn(v1.z * inv, v1.w * inv);
    *reinterpret_cast<uint4*>(dst + (size_t)r * DIM + lane * 8) = *reinterpret_cast<uint4*>(h);
    if (lane == 0) nsq[r] = ss * inv * inv;
}

__global__ __launch_bounds__(256) void normalize_c_kernel(const float* __restrict__ c) {
    int row = blockIdx.x * 8 + (threadIdx.x >> 5);
    norm_row(c, g_ch, g_nc, row, threadIdx.x & 31);
}

__global__ __launch_bounds__(256) void normalize_zp_kernel(const float* __restrict__ z,
                                                           const float* __restrict__ p) {
    int row = blockIdx.x * 8 + (threadIdx.x >> 5);
    int lane = threadIdx.x & 31;
    if (row < TWO_B) norm_row(z, g_zh, g_nz, row, lane);
    else             norm_row(p, g_ph, g_np, row - TWO_B, lane);
}

// ---------------- fp16 HMMA GEMM + fused distance/exp epilogue ----------------
// grid = (KC/BN, TWO_B/BM, 2), block = 512 (16 warps, 4x4), warp tile 32x32.
// BK = 64 per stage, 2-stage double buffer.
#define NSTG 4            // K stages: 256 / 64
#define ROWB 144          // 64 halves payload + 8 pad = 144 bytes per row
#define STAGE_B (128 * ROWB)          // 18432 B per tile per stage
#define SMEM_TOTAL (4 * STAGE_B + 512)

__global__ __launch_bounds__(512, 2) void gemm_dist_hmma() {
    extern __shared__ char dsm[];
    uint32_t sA = smem_u32(dsm);                 // A: 2 stages
    uint32_t sB = sA + 2 * STAGE_B;              // B: 2 stages
    float* colacc = reinterpret_cast<float*>(dsm + 4 * STAGE_B);

    int tid = threadIdx.x;
    int lane = tid & 31;
    int wid = tid >> 5;
    int wm = wid >> 2;   // 0..3  (32-row band)
    int wn = wid & 3;    // 0..3  (32-col band)
    int q = lane & 3;
    int gr = lane >> 2;

    int which = blockIdx.z;
    int bm = blockIdx.y;
    int bn = blockIdx.x;

    const __half* Ag = (which ? g_ph : g_zh) + (size_t)(bm * BM) * DIM;
    const __half* Bg = g_ch + (size_t)(bn * BN) * DIM;
    const float* na = which ? g_np : g_nz;
    __half* T = which ? g_tp : g_tz;

    // loaders: 512 threads, 2 tiles, 128 rows each, 2 threads per row
    int ltile = tid >> 8;         // 0 = A, 1 = B
    int local = tid & 255;
    int lrow = local >> 1;        // 0..127
    int lhalf = local & 1;        // which 64-byte half of the 128B row
    const __half* gsrc = (ltile ? Bg : Ag) + (size_t)lrow * DIM + lhalf * 32;
    uint32_t sdst = (ltile ? sB : sA) + lrow * ROWB + lhalf * 64;

    float acc[2][4][4];
    #pragma unroll
    for (int i = 0; i < 2; i++)
        #pragma unroll
        for (int j = 0; j < 4; j++)
            #pragma unroll
            for (int k = 0; k < 4; k++)
                acc[i][j][k] = 0.0f;

    // prologue: issue stage 0 into buf 0
    #pragma unroll
    for (int c2 = 0; c2 < 4; c2++)
        CP_ASYNC16(sdst + c2 * 16, gsrc + c2 * 8);
    CP_COMMIT();

    uint32_t aBase = sA + (wm * 32 + (lane & 15)) * ROWB + (lane >> 4) * 16;
    uint32_t bBase = sB + (wn * 32 + (lane & 7) + ((lane >> 4) << 3)) * ROWB
                     + ((lane >> 3) & 1) * 16;

    #pragma unroll
    for (int s = 0; s < NSTG; s++) {
        CP_WAIT(0);             // stage s data present
        __syncthreads();        // all warps done with the other buffer

        if (s + 1 < NSTG) {
            uint32_t d = sdst + ((s + 1) & 1) * STAGE_B;
            const __half* g = gsrc + (s + 1) * 64;
            #pragma unroll
            for (int c2 = 0; c2 < 4; c2++)
                CP_ASYNC16(d + c2 * 16, g + c2 * 8);
            CP_COMMIT();
        }

        uint32_t aB = aBase + (s & 1) * STAGE_B;
        uint32_t bB = bBase + (s & 1) * STAGE_B;
        #pragma unroll
        for (int k16 = 0; k16 < 4; k16++) {
            uint32_t a[2][4], b[2][4];
            #pragma unroll
            for (int mt = 0; mt < 2; mt++)
                LDSM_X4(a[mt][0], a[mt][1], a[mt][2], a[mt][3],
                        aB + mt * (16 * ROWB) + k16 * 32);
            #pragma unroll
            for (int j = 0; j < 2; j++)
                LDSM_X4(b[j][0], b[j][1], b[j][2], b[j][3],
                        bB + j * (16 * ROWB) + k16 * 32);
            #pragma unroll
            for (int mt = 0; mt < 2; mt++)
                #pragma unroll
                for (int nt = 0; nt < 4; nt++)
                    mma_f16(acc[mt][nt], a[mt], &b[nt >> 1][(nt & 1) * 2]);
        }
    }
    __syncthreads();

    // ---------------- epilogue ----------------
    if (tid < BN) colacc[tid] = 0.0f;
    __syncthreads();

    float nc0v[4], nc1v[4];
    #pragma unroll
    for (int nt = 0; nt < 4; nt++) {
        int c = bn * BN + wn * 32 + nt * 8 + 2 * q;
        nc0v[nt] = g_nc[c];
        nc1v[nt] = g_nc[c + 1];
    }

    float es0[4], es1[4];
    #pragma unroll
    for (int nt = 0; nt < 4; nt++) { es0[nt] = 0.f; es1[nt] = 0.f; }

    #pragma unroll
    for (int mt = 0; mt < 2; mt++) {
        int r = bm * BM + wm * 32 + mt * 16 + gr;
        float na0 = na[r], na1 = na[r + 8];
        #pragma unroll
        for (int nt = 0; nt < 4; nt++) {
            int c = bn * BN + wn * 32 + nt * 8 + 2 * q;
            float t00 = distf(na0 + nc0v[nt] - 2.0f * acc[mt][nt][0]);
            float t01 = distf(na0 + nc1v[nt] - 2.0f * acc[mt][nt][1]);
            float t10 = distf(na1 + nc0v[nt] - 2.0f * acc[mt][nt][2]);
            float t11 = distf(na1 + nc1v[nt] - 2.0f * acc[mt][nt][3]);
            *(__half2*)&T[(size_t)r * KC + c]       = __floats2half2_rn(t00, t01);
            *(__half2*)&T[(size_t)(r + 8) * KC + c] = __floats2half2_rn(t10, t11);
            es0[nt] += __expf(t00) + __expf(t10);
            es1[nt] += __expf(t01) + __expf(t11);
        }
    }

    #pragma unroll
    for (int nt = 0; nt < 4; nt++) {
        int cl = wn * 32 + nt * 8 + 2 * q;
        atomicAdd(&colacc[cl], es0[nt]);
        atomicAdd(&colacc[cl + 1], es1[nt]);
    }
    __syncthreads();

    int csbase = (which * 2 + (bm >> 7)) * KC;
    if (tid < BN)
        atomicAdd(&g_cs[csbase + bn * BN + tid], colacc[tid]);
}

// ---------------- tail kernels ----------------
__global__ void logcs_kernel() {
    int i = blockIdx.x * blockDim.x + threadIdx.x;
    if (i < 4 * KC) g_lcs[i] = logf(g_cs[i]);
}

__global__ __launch_bounds__(256) void final_kernel() {
    __shared__ float sm[32];
    int b = blockIdx.x;
    int t = threadIdx.x;
    int lane = t & 31;
    int wid = t >> 5;
    int k0 = t * 4;

    uint2 rz1 = *(const uint2*)(g_tz + (size_t)b * KC + k0);
    uint2 rz2 = *(const uint2*)(g_tz + (size_t)(b + B_HALF) * KC + k0);
    uint2 rp1 = *(const uint2*)(g_tp + (size_t)b * KC + k0);
    uint2 rp2 = *(const uint2*)(g_tp + (size_t)(b + B_HALF) * KC + k0);
    float4 l1 = *(const float4*)(g_lcs + k0);
    float4 l2 = *(const float4*)(g_lcs + KC + k0);
    float4 l3 = *(const float4*)(g_lcs + 2 * KC + k0);
    float4 l4 = *(const float4*)(g_lcs + 3 * KC + k0);

    float tz1[4], tz2[4], tp1[4], tp2[4];
    {
        float2 a, bb;
        a = __half22float2(*(__half2*)&rz1.x); bb = __half22float2(*(__half2*)&rz1.y);
        tz1[0] = a.x; tz1[1] = a.y; tz1[2] = bb.x; tz1[3] = bb.y;
        a = __half22float2(*(__half2*)&rz2.x); bb = __half22float2(*(__half2*)&rz2.y);
        tz2[0] = a.x; tz2[1] = a.y; tz2[2] = bb.x; tz2[3] = bb.y;
        a = __half22float2(*(__half2*)&rp1.x); bb = __half22float2(*(__half2*)&rp1.y);
        tp1[0] = a.x; tp1[1] = a.y; tp1[2] = bb.x; tp1[3] = bb.y;
        a = __half22float2(*(__half2*)&rp2.x); bb = __half22float2(*(__half2*)&rp2.y);
        tp2[0] = a.x; tp2[1] = a.y; tp2[2] = bb.x; tp2[3] = bb.y;
    }
    float lc1[4] = {l1.x, l1.y, l1.z, l1.w};
    float lc2[4] = {l2.x, l2.y, l2.z, l2.w};
    float lc3[4] = {l3.x, l3.y, l3.z, l3.w};
    float lc4[4] = {l4.x, l4.y, l4.z, l4.w};

    float az1[4], az2[4], lp[4];
    float az1s = 0.f, az2s = 0.f, ap1s = 0.f, ap2s = 0.f;
    #pragma unroll
    for (int j = 0; j < 4; j++) {
        float u1 = tz1[j] - lc1[j];
        float u2 = tz2[j] - lc2[j];
        float v1 = tp1[j] - lc3[j];
        float v2 = tp2[j] - lc4[j];
        az1[j] = __expf(u1); az1s += az1[j];
        az2[j] = __expf(u2); az2s += az2[j];
        ap1s += __expf(v1);
        ap2s += __expf(v2);
        lp[j] = v1 + v2;
    }

    #pragma unroll
    for (int o = 16; o > 0; o >>= 1) {
        az1s += __shfl_xor_sync(0xffffffffu, az1s, o);
        az2s += __shfl_xor_sync(0xffffffffu, az2s, o);
        ap1s += __shfl_xor_sync(0xffffffffu, ap1s, o);
        ap2s += __shfl_xor_sync(0xffffffffu, ap2s, o);
    }
    if (lane == 0) {
        sm[wid * 4 + 0] = az1s; sm[wid * 4 + 1] = az2s;
        sm[wid * 4 + 2] = ap1s; sm[wid * 4 + 3] = ap2s;
    }
    __syncthreads();
    if (t < 32) {
        float v = sm[t];
        v += __shfl_xor_sync(0xffffffffu, v, 4);
        v += __shfl_xor_sync(0xffffffffu, v, 8);
        v += __shfl_xor_sync(0xffffffffu, v, 16);
        if (t < 4) sm[t] = v;
    }
    __syncthreads();
    float rz1s = sm[0], rz2s = sm[1], rp1s = sm[2], rp2s = sm[3];

    float lr = logf(rp1s) + logf(rp2s);
    float irz1 = 1.0f / rz1s;
    float irz2 = 1.0f / rz2s;
    float dot = 0.f;
    #pragma unroll
    for (int j = 0; j < 4; j++)
        dot += (az1[j] * irz1 + az2[j] * irz2) * (lp[j] - lr);

    #pragma unroll
    for (int o = 16; o > 0; o >>= 1)
        dot += __shfl_xor_sync(0xffffffffu, dot, o);
    if (lane == 0) sm[8 + wid] = dot;
    __syncthreads();
    if (t < 32) {
        float v = (t < 8) ? sm[8 + t] : 0.f;
        v += __shfl_xor_sync(0xffffffffu, v, 1);
        v += __shfl_xor_sync(0xffffffffu, v, 2);
        v += __shfl_xor_sync(0xffffffffu, v, 4);
        if (t == 0)
            atomicAdd(&g_loss, -(double)v / (4.0 * (double)B_HALF));
    }
}

__global__ void finalize_kernel(float* out) {
    out[0] = (float)g_loss;
}

// ---------------- launch ----------------
extern "C" void kernel_launch(void* const* d_in, const int* in_sizes, int n_in,
                              void* d_out, int out_size) {
    const float* z = (const float*)d_in[0];
    const float* p = (const float*)d_in[1];
    const float* c = (const float*)d_in[2];
    float* out = (float*)d_out;

    cudaFuncSetAttribute(gemm_dist_hmma, cudaFuncAttributeMaxDynamicSharedMemorySize, SMEM_TOTAL);

    zero_kernel<<<16, 256>>>();
    normalize_c_kernel<<<KC / 8, 256>>>(c);
    normalize_zp_kernel<<<2 * TWO_B / 8, 256>>>(z, p);
    dim3 ggrid(KC / BN, TWO_B / BM, 2);
    gemm_dist_hmma<<<ggrid, 512, SMEM_TOTAL>>>();
    logcs_kernel<<<16, 256>>>();
    final_kernel<<<B_HALF, 256>>>();
    finalize_kernel<<<1, 1>>>(out);
}

// round 9
// speedup vs baseline: 1.3100x; 1.2034x over previous
#include <cuda_runtime.h>
#include <cuda_fp16.h>
#include <math.h>
#include <stdint.h>

#define TWO_B 32768
#define B_HALF 16384
#define DIM 256
#define KC 1024
#define BM 128
#define BN 128

// ---------------- device scratch (static, no allocation) ----------------
__device__ __align__(16) int8_t g_zq[(size_t)TWO_B * DIM];
__device__ __align__(16) int8_t g_pq[(size_t)TWO_B * DIM];
__device__ __align__(16) int8_t g_cq[(size_t)KC * DIM];
__device__ float g_rsz[TWO_B];       // per-row dequant scale (max/127)
__device__ float g_rsp[TWO_B];
__device__ float g_rsc[KC];
__device__ float g_nz[TWO_B];
__device__ float g_np[TWO_B];
__device__ float g_nc[KC];
__device__ __align__(16) __half g_tz[(size_t)TWO_B * KC];   // t stored fp16 (64 MB)
__device__ __align__(16) __half g_tp[(size_t)TWO_B * KC];
__device__ float g_cs[4 * KC];
__device__ float g_lcs[4 * KC];
__device__ double g_loss;

// ---------------- PTX helpers ----------------
__device__ __forceinline__ uint32_t smem_u32(const void* p) {
    uint32_t a;
    asm("{ .reg .u64 t; cvta.to.shared.u64 t, %1; cvt.u32.u64 %0, t; }" : "=r"(a) : "l"(p));
    return a;
}
#define CP_ASYNC16(dst, src) \
    asm volatile("cp.async.cg.shared.global [%0], [%1], 16;" :: "r"(dst), "l"(src) : "memory")
#define CP_COMMIT() asm volatile("cp.async.commit_group;" ::: "memory")
#define CP_WAIT(n)  asm volatile("cp.async.wait_group %0;" :: "n"(n) : "memory")
#define LDSM_X4(r0, r1, r2, r3, addr) \
    asm volatile("ldmatrix.sync.aligned.m8n8.x4.shared.b16 {%0,%1,%2,%3}, [%4];" \
                 : "=r"(r0), "=r"(r1), "=r"(r2), "=r"(r3) : "r"(addr))

// int8 IMMA m16n8k32, s32 accumulate
__device__ __forceinline__ void mma_s8(int* c, const uint32_t* a, const uint32_t* b) {
    asm volatile(
        "mma.sync.aligned.m16n8k32.row.col.s32.s8.s8.s32 "
        "{%0,%1,%2,%3}, {%4,%5,%6,%7}, {%8,%9}, {%0,%1,%2,%3};"
        : "+r"(c[0]), "+r"(c[1]), "+r"(c[2]), "+r"(c[3])
        : "r"(a[0]), "r"(a[1]), "r"(a[2]), "r"(a[3]), "r"(b[0]), "r"(b[1]));
}

__device__ __forceinline__ float distf(float sq) {
    return 20.0f * sqrtf(fmaxf(sq, 1e-12f));
}

// ---------------- small kernels ----------------
__global__ void zero_kernel() {
    int i = blockIdx.x * blockDim.x + threadIdx.x;
    if (i < 4 * KC) g_cs[i] = 0.0f;
    if (i == 0) g_loss = 0.0;
}

// one warp per row: normalize, per-row max-scale int8 quantization
__device__ __forceinline__ void norm_row_q(const float* __restrict__ src,
                                           int8_t* __restrict__ dstq,
                                           float* __restrict__ rs,
                                           float* __restrict__ nsq, int r, int lane) {
    const float4* s4 = reinterpret_cast<const float4*>(src + (size_t)r * DIM);
    float4 v0 = s4[lane * 2];
    float4 v1 = s4[lane * 2 + 1];
    float ss = v0.x * v0.x + v0.y * v0.y + v0.z * v0.z + v0.w * v0.w
             + v1.x * v1.x + v1.y * v1.y + v1.z * v1.z + v1.w * v1.w;
    #pragma unroll
    for (int o = 16; o > 0; o >>= 1)
        ss += __shfl_xor_sync(0xffffffffu, ss, o);
    float inv = 1.0f / fmaxf(sqrtf(ss), 1e-12f);

    float x[8] = {v0.x * inv, v0.y * inv, v0.z * inv, v0.w * inv,
                  v1.x * inv, v1.y * inv, v1.z * inv, v1.w * inv};
    float m = 0.f;
    #pragma unroll
    for (int j = 0; j < 8; j++) m = fmaxf(m, fabsf(x[j]));
    #pragma unroll
    for (int o = 16; o > 0; o >>= 1)
        m = fmaxf(m, __shfl_xor_sync(0xffffffffu, m, o));

    float s = 127.0f / m;
    int q[8];
    #pragma unroll
    for (int j = 0; j < 8; j++) q[j] = __float2int_rn(x[j] * s);
    uint32_t lo = (q[0] & 0xff) | ((q[1] & 0xff) << 8) | ((q[2] & 0xff) << 16) | ((q[3] & 0xff) << 24);
    uint32_t hi = (q[4] & 0xff) | ((q[5] & 0xff) << 8) | ((q[6] & 0xff) << 16) | ((q[7] & 0xff) << 24);
    *reinterpret_cast<uint2*>(dstq + (size_t)r * DIM + lane * 8) = make_uint2(lo, hi);
    if (lane == 0) {
        rs[r] = m * (1.0f / 127.0f);
        nsq[r] = ss * inv * inv;
    }
}

__global__ __launch_bounds__(256) void normalize_kernel(const float* __restrict__ z,
                                                        const float* __restrict__ p,
                                                        const float* __restrict__ c) {
    int row = blockIdx.x * 8 + (threadIdx.x >> 5);
    int lane = threadIdx.x & 31;
    if (row < TWO_B)          norm_row_q(z, g_zq, g_rsz, g_nz, row, lane);
    else if (row < 2 * TWO_B) norm_row_q(p, g_pq, g_rsp, g_np, row - TWO_B, lane);
    else                      norm_row_q(c, g_cq, g_rsc, g_nc, row - 2 * TWO_B, lane);
}

// ---------------- int8 IMMA GEMM + fused distance/exp epilogue ----------------
// grid = (KC/BN, TWO_B/BM, 2), block = 512 (16 warps, 4x4), warp tile 32x32.
// BK = 128 bytes per stage, 2-stage double buffer, 4 k32 steps per stage.
#define NSTG 2
#define ROWB 144          // 128 payload + 16 pad bytes per row
#define STAGE_B (128 * ROWB)          // 18432 B per tile per stage
#define SMEM_TOTAL (4 * STAGE_B + 512)

__global__ __launch_bounds__(512, 2) void gemm_dist_imma() {
    extern __shared__ char dsm[];
    uint32_t sA = smem_u32(dsm);                 // A: 2 stages
    uint32_t sB = sA + 2 * STAGE_B;              // B: 2 stages
    float* colacc = reinterpret_cast<float*>(dsm + 4 * STAGE_B);

    int tid = threadIdx.x;
    int lane = tid & 31;
    int wid = tid >> 5;
    int wm = wid >> 2;   // 0..3  (32-row band)
    int wn = wid & 3;    // 0..3  (32-col band)
    int q = lane & 3;
    int gr = lane >> 2;

    int which = blockIdx.z;
    int bm = blockIdx.y;
    int bn = blockIdx.x;

    const int8_t* Ag = (which ? g_pq : g_zq) + (size_t)(bm * BM) * DIM;
    const int8_t* Bg = g_cq + (size_t)(bn * BN) * DIM;
    const float* na = which ? g_np : g_nz;
    const float* rsa = which ? g_rsp : g_rsz;
    __half* T = which ? g_tp : g_tz;

    // loaders: 512 threads, 2 tiles, 128 rows each, 2 threads per row (64 B each)
    int ltile = tid >> 8;         // 0 = A, 1 = B
    int local = tid & 255;
    int lrow = local >> 1;        // 0..127
    int lhalf = local & 1;        // which 64-byte half of the 128B stage-row
    const int8_t* gsrc = (ltile ? Bg : Ag) + (size_t)lrow * DIM + lhalf * 64;
    uint32_t sdst = (ltile ? sB : sA) + lrow * ROWB + lhalf * 64;

    int acc[2][4][4];
    #pragma unroll
    for (int i = 0; i < 2; i++)
        #pragma unroll
        for (int j = 0; j < 4; j++)
            #pragma unroll
            for (int k = 0; k < 4; k++)
                acc[i][j][k] = 0;

    // prologue: stage 0 into buf 0
    #pragma unroll
    for (int c2 = 0; c2 < 4; c2++)
        CP_ASYNC16(sdst + c2 * 16, gsrc + c2 * 16);
    CP_COMMIT();

    uint32_t aBase = sA + (wm * 32 + (lane & 15)) * ROWB + (lane >> 4) * 16;
    uint32_t bBase = sB + (wn * 32 + (lane & 7) + ((lane >> 4) << 3)) * ROWB
                     + ((lane >> 3) & 1) * 16;

    #pragma unroll
    for (int s = 0; s < NSTG; s++) {
        CP_WAIT(0);             // stage s present
        __syncthreads();

        if (s + 1 < NSTG) {
            uint32_t d = sdst + STAGE_B;
            const int8_t* g = gsrc + 128;
            #pragma unroll
            for (int c2 = 0; c2 < 4; c2++)
                CP_ASYNC16(d + c2 * 16, g + c2 * 16);
            CP_COMMIT();
        }

        uint32_t aB = aBase + s * STAGE_B;
        uint32_t bB = bBase + s * STAGE_B;
        #pragma unroll
        for (int k32 = 0; k32 < 4; k32++) {
            uint32_t a[2][4], b[2][4];
            #pragma unroll
            for (int mt = 0; mt < 2; mt++)
                LDSM_X4(a[mt][0], a[mt][1], a[mt][2], a[mt][3],
                        aB + mt * (16 * ROWB) + k32 * 32);
            #pragma unroll
            for (int j = 0; j < 2; j++)
                LDSM_X4(b[j][0], b[j][1], b[j][2], b[j][3],
                        bB + j * (16 * ROWB) + k32 * 32);
            #pragma unroll
            for (int mt = 0; mt < 2; mt++)
                #pragma unroll
                for (int nt = 0; nt < 4; nt++)
                    mma_s8(acc[mt][nt], a[mt], &b[nt >> 1][(nt & 1) * 2]);
        }
    }
    __syncthreads();

    // ---------------- epilogue ----------------
    if (tid < BN) colacc[tid] = 0.0f;
    __syncthreads();

    float nc0v[4], nc1v[4], rb0[4], rb1[4];
    #pragma unroll
    for (int nt = 0; nt < 4; nt++) {
        int c = bn * BN + wn * 32 + nt * 8 + 2 * q;
        nc0v[nt] = g_nc[c];
        nc1v[nt] = g_nc[c + 1];
        rb0[nt] = g_rsc[c];
        rb1[nt] = g_rsc[c + 1];
    }

    float es0[4], es1[4];
    #pragma unroll
    for (int nt = 0; nt < 4; nt++) { es0[nt] = 0.f; es1[nt] = 0.f; }

    #pragma unroll
    for (int mt = 0; mt < 2; mt++) {
        int r = bm * BM + wm * 32 + mt * 16 + gr;
        float na0 = na[r], na1 = na[r + 8];
        float ra0 = rsa[r], ra1 = rsa[r + 8];
        #pragma unroll
        for (int nt = 0; nt < 4; nt++) {
            int c = bn * BN + wn * 32 + nt * 8 + 2 * q;
            float g00 = (float)acc[mt][nt][0] * (ra0 * rb0[nt]);
            float g01 = (float)acc[mt][nt][1] * (ra0 * rb1[nt]);
            float g10 = (float)acc[mt][nt][2] * (ra1 * rb0[nt]);
            float g11 = (float)acc[mt][nt][3] * (ra1 * rb1[nt]);
            float t00 = distf(na0 + nc0v[nt] - 2.0f * g00);
            float t01 = distf(na0 + nc1v[nt] - 2.0f * g01);
            float t10 = distf(na1 + nc0v[nt] - 2.0f * g10);
            float t11 = distf(na1 + nc1v[nt] - 2.0f * g11);
            *(__half2*)&T[(size_t)r * KC + c]       = __floats2half2_rn(t00, t01);
            *(__half2*)&T[(size_t)(r + 8) * KC + c] = __floats2half2_rn(t10, t11);
            es0[nt] += __expf(t00) + __expf(t10);
            es1[nt] += __expf(t01) + __expf(t11);
        }
    }

    #pragma unroll
    for (int nt = 0; nt < 4; nt++) {
        int cl = wn * 32 + nt * 8 + 2 * q;
        atomicAdd(&colacc[cl], es0[nt]);
        atomicAdd(&colacc[cl + 1], es1[nt]);
    }
    __syncthreads();

    int csbase = (which * 2 + (bm >> 7)) * KC;
    if (tid < BN)
        atomicAdd(&g_cs[csbase + bn * BN + tid], colacc[tid]);
}

// ---------------- tail kernels ----------------
__global__ void logcs_kernel() {
    int i = blockIdx.x * blockDim.x + threadIdx.x;
    if (i < 4 * KC) g_lcs[i] = logf(g_cs[i]);
}

__global__ __launch_bounds__(256) void final_kernel() {
    __shared__ float sm[32];
    int b = blockIdx.x;
    int t = threadIdx.x;
    int lane = t & 31;
    int wid = t >> 5;
    int k0 = t * 4;

    uint2 rz1 = *(const uint2*)(g_tz + (size_t)b * KC + k0);
    uint2 rz2 = *(const uint2*)(g_tz + (size_t)(b + B_HALF) * KC + k0);
    uint2 rp1 = *(const uint2*)(g_tp + (size_t)b * KC + k0);
    uint2 rp2 = *(const uint2*)(g_tp + (size_t)(b + B_HALF) * KC + k0);
    float4 l1 = *(const float4*)(g_lcs + k0);
    float4 l2 = *(const float4*)(g_lcs + KC + k0);
    float4 l3 = *(const float4*)(g_lcs + 2 * KC + k0);
    float4 l4 = *(const float4*)(g_lcs + 3 * KC + k0);

    float tz1[4], tz2[4], tp1[4], tp2[4];
    {
        float2 a, bb;
        a = __half22float2(*(__half2*)&rz1.x); bb = __half22float2(*(__half2*)&rz1.y);
        tz1[0] = a.x; tz1[1] = a.y; tz1[2] = bb.x; tz1[3] = bb.y;
        a = __half22float2(*(__half2*)&rz2.x); bb = __half22float2(*(__half2*)&rz2.y);
        tz2[0] = a.x; tz2[1] = a.y; tz2[2] = bb.x; tz2[3] = bb.y;
        a = __half22float2(*(__half2*)&rp1.x); bb = __half22float2(*(__half2*)&rp1.y);
        tp1[0] = a.x; tp1[1] = a.y; tp1[2] = bb.x; tp1[3] = bb.y;
        a = __half22float2(*(__half2*)&rp2.x); bb = __half22float2(*(__half2*)&rp2.y);
        tp2[0] = a.x; tp2[1] = a.y; tp2[2] = bb.x; tp2[3] = bb.y;
    }
    float lc1[4] = {l1.x, l1.y, l1.z, l1.w};
    float lc2[4] = {l2.x, l2.y, l2.z, l2.w};
    float lc3[4] = {l3.x, l3.y, l3.z, l3.w};
    float lc4[4] = {l4.x, l4.y, l4.z, l4.w};

    float az1[4], az2[4], lp[4];
    float az1s = 0.f, az2s = 0.f, ap1s = 0.f, ap2s = 0.f;
    #pragma unroll
    for (int j = 0; j < 4; j++) {
        float u1 = tz1[j] - lc1[j];
        float u2 = tz2[j] - lc2[j];
        float v1 = tp1[j] - lc3[j];
        float v2 = tp2[j] - lc4[j];
        az1[j] = __expf(u1); az1s += az1[j];
        az2[j] = __expf(u2); az2s += az2[j];
        ap1s += __expf(v1);
        ap2s += __expf(v2);
        lp[j] = v1 + v2;
    }

    #pragma unroll
    for (int o = 16; o > 0; o >>= 1) {
        az1s += __shfl_xor_sync(0xffffffffu, az1s, o);
        az2s += __shfl_xor_sync(0xffffffffu, az2s, o);
        ap1s += __shfl_xor_sync(0xffffffffu, ap1s, o);
        ap2s += __shfl_xor_sync(0xffffffffu, ap2s, o);
    }
    if (lane == 0) {
        sm[wid * 4 + 0] = az1s; sm[wid * 4 + 1] = az2s;
        sm[wid * 4 + 2] = ap1s; sm[wid * 4 + 3] = ap2s;
    }
    __syncthreads();
    if (t < 32) {
        float v = sm[t];
        v += __shfl_xor_sync(0xffffffffu, v, 4);
        v += __shfl_xor_sync(0xffffffffu, v, 8);
        v += __shfl_xor_sync(0xffffffffu, v, 16);
        if (t < 4) sm[t] = v;
    }
    __syncthreads();
    float rz1s = sm[0], rz2s = sm[1], rp1s = sm[2], rp2s = sm[3];

    float lr = logf(rp1s) + logf(rp2s);
    float irz1 = 1.0f / rz1s;
    float irz2 = 1.0f / rz2s;
    float dot = 0.f;
    #pragma unroll
    for (int j = 0; j < 4; j++)
        dot += (az1[j] * irz1 + az2[j] * irz2) * (lp[j] - lr);

    #pragma unroll
    for (int o = 16; o > 0; o >>= 1)
        dot += __shfl_xor_sync(0xffffffffu, dot, o);
    if (lane == 0) sm[8 + wid] = dot;
    __syncthreads();
    if (t < 32) {
        float v = (t < 8) ? sm[8 + t] : 0.f;
        v += __shfl_xor_sync(0xffffffffu, v, 1);
        v += __shfl_xor_sync(0xffffffffu, v, 2);
        v += __shfl_xor_sync(0xffffffffu, v, 4);
        if (t == 0)
            atomicAdd(&g_loss, -(double)v / (4.0 * (double)B_HALF));
    }
}

__global__ void finalize_kernel(float* out) {
    out[0] = (float)g_loss;
}

// ---------------- launch ----------------
extern "C" void kernel_launch(void* const* d_in, const int* in_sizes, int n_in,
                              void* d_out, int out_size) {
    const float* z = (const float*)d_in[0];
    const float* p = (const float*)d_in[1];
    const float* c = (const float*)d_in[2];
    float* out = (float*)d_out;

    cudaFuncSetAttribute(gemm_dist_imma, cudaFuncAttributeMaxDynamicSharedMemorySize, SMEM_TOTAL);

    zero_kernel<<<16, 256>>>();
    normalize_kernel<<<(2 * TWO_B + KC) / 8, 256>>>(z, p, c);
    dim3 ggrid(KC / BN, TWO_B / BM, 2);
    gemm_dist_imma<<<ggrid, 512, SMEM_TOTAL>>>();
    logcs_kernel<<<16, 256>>>();
    final_kernel<<<B_HALF, 256>>>();
    finalize_kernel<<<1, 1>>>(out);
}

// round 10
// speedup vs baseline: 1.6974x; 1.2957x over previous
#include <cuda_runtime.h>
#include <cuda_fp16.h>
#include <math.h>
#include <stdint.h>

#define TWO_B 32768
#define B_HALF 16384
#define DIM 256
#define KC 1024
#define BM 128
#define BN 128

// ---------------- device scratch (static, no allocation) ----------------
__device__ __align__(16) int8_t g_zq[(size_t)TWO_B * DIM];
__device__ __align__(16) int8_t g_pq[(size_t)TWO_B * DIM];
__device__ __align__(16) int8_t g_cq[(size_t)KC * DIM];
__device__ float g_rsz[TWO_B];       // per-row dequant scale (max/127)
__device__ float g_rsp[TWO_B];
__device__ float g_rsc[KC];
__device__ float g_nz[TWO_B];
__device__ float g_np[TWO_B];
__device__ float g_nc[KC];
__device__ __align__(16) __half g_tz[(size_t)TWO_B * KC];   // t stored fp16 (64 MB)
__device__ __align__(16) __half g_tp[(size_t)TWO_B * KC];
__device__ float g_cs[4 * KC];
__device__ float g_lcs[4 * KC];
__device__ double g_loss;

// ---------------- PTX helpers ----------------
__device__ __forceinline__ uint32_t smem_u32(const void* p) {
    uint32_t a;
    asm("{ .reg .u64 t; cvta.to.shared.u64 t, %1; cvt.u32.u64 %0, t; }" : "=r"(a) : "l"(p));
    return a;
}
#define CP_ASYNC16(dst, src) \
    asm volatile("cp.async.cg.shared.global [%0], [%1], 16;" :: "r"(dst), "l"(src) : "memory")
#define CP_COMMIT() asm volatile("cp.async.commit_group;" ::: "memory")
#define CP_WAIT(n)  asm volatile("cp.async.wait_group %0;" :: "n"(n) : "memory")
#define LDSM_X4(r0, r1, r2, r3, addr) \
    asm volatile("ldmatrix.sync.aligned.m8n8.x4.shared.b16 {%0,%1,%2,%3}, [%4];" \
                 : "=r"(r0), "=r"(r1), "=r"(r2), "=r"(r3) : "r"(addr))

// int8 IMMA m16n8k32, s32 accumulate
__device__ __forceinline__ void mma_s8(int* c, const uint32_t* a, const uint32_t* b) {
    asm volatile(
        "mma.sync.aligned.m16n8k32.row.col.s32.s8.s8.s32 "
        "{%0,%1,%2,%3}, {%4,%5,%6,%7}, {%8,%9}, {%0,%1,%2,%3};"
        : "+r"(c[0]), "+r"(c[1]), "+r"(c[2]), "+r"(c[3])
        : "r"(a[0]), "r"(a[1]), "r"(a[2]), "r"(a[3]), "r"(b[0]), "r"(b[1]));
}

__device__ __forceinline__ float distf(float sq) {
    return 20.0f * sqrtf(fmaxf(sq, 1e-12f));
}

// ---------------- normalize + quantize (+ zero fold-in) ----------------
__device__ __forceinline__ void norm_row_q(const float* __restrict__ src,
                                           int8_t* __restrict__ dstq,
                                           float* __restrict__ rs,
                                           float* __restrict__ nsq, int r, int lane) {
    const float4* s4 = reinterpret_cast<const float4*>(src + (size_t)r * DIM);
    float4 v0 = s4[lane * 2];
    float4 v1 = s4[lane * 2 + 1];
    float ss = v0.x * v0.x + v0.y * v0.y + v0.z * v0.z + v0.w * v0.w
             + v1.x * v1.x + v1.y * v1.y + v1.z * v1.z + v1.w * v1.w;
    #pragma unroll
    for (int o = 16; o > 0; o >>= 1)
        ss += __shfl_xor_sync(0xffffffffu, ss, o);
    float inv = 1.0f / fmaxf(sqrtf(ss), 1e-12f);

    float x[8] = {v0.x * inv, v0.y * inv, v0.z * inv, v0.w * inv,
                  v1.x * inv, v1.y * inv, v1.z * inv, v1.w * inv};
    float m = 0.f;
    #pragma unroll
    for (int j = 0; j < 8; j++) m = fmaxf(m, fabsf(x[j]));
    #pragma unroll
    for (int o = 16; o > 0; o >>= 1)
        m = fmaxf(m, __shfl_xor_sync(0xffffffffu, m, o));

    float s = 127.0f / m;
    int q[8];
    #pragma unroll
    for (int j = 0; j < 8; j++) q[j] = __float2int_rn(x[j] * s);
    uint32_t lo = (q[0] & 0xff) | ((q[1] & 0xff) << 8) | ((q[2] & 0xff) << 16) | ((q[3] & 0xff) << 24);
    uint32_t hi = (q[4] & 0xff) | ((q[5] & 0xff) << 8) | ((q[6] & 0xff) << 16) | ((q[7] & 0xff) << 24);
    *reinterpret_cast<uint2*>(dstq + (size_t)r * DIM + lane * 8) = make_uint2(lo, hi);
    if (lane == 0) {
        rs[r] = m * (1.0f / 127.0f);
        nsq[r] = ss * inv * inv;
    }
}

__global__ __launch_bounds__(256) void normalize_kernel(const float* __restrict__ z,
                                                        const float* __restrict__ p,
                                                        const float* __restrict__ c) {
    if (blockIdx.x == 0) {      // fold in the zeroing
        int t = threadIdx.x;
        #pragma unroll
        for (int j = 0; j < 16; j++) g_cs[t + j * 256] = 0.0f;
        if (t == 0) g_loss = 0.0;
    }
    int row = blockIdx.x * 8 + (threadIdx.x >> 5);
    int lane = threadIdx.x & 31;
    if (row < TWO_B)          norm_row_q(z, g_zq, g_rsz, g_nz, row, lane);
    else if (row < 2 * TWO_B) norm_row_q(p, g_pq, g_rsp, g_np, row - TWO_B, lane);
    else                      norm_row_q(c, g_cq, g_rsc, g_nc, row - 2 * TWO_B, lane);
}

// ---------------- int8 IMMA GEMM + fused distance/exp epilogue ----------------
// grid = (KC/BN, TWO_B/BM, 2), block = 512 (16 warps, 4x4), warp tile 32x32.
// Single stage: full K=256 bytes per row in SMEM; one sync in mainloop.
#define ROWB 272          // 256 payload + 16 pad bytes per row
#define TILE_BYTES (128 * ROWB)       // 34816 per tile
#define SMEM_TOTAL (2 * TILE_BYTES)

__global__ __launch_bounds__(512, 2) void gemm_dist_imma() {
    extern __shared__ char dsm[];
    uint32_t sA = smem_u32(dsm);
    uint32_t sB = sA + TILE_BYTES;

    int tid = threadIdx.x;
    int lane = tid & 31;
    int wid = tid >> 5;
    int wm = wid >> 2;   // 0..3  (32-row band)
    int wn = wid & 3;    // 0..3  (32-col band)
    int q = lane & 3;
    int gr = lane >> 2;

    int which = blockIdx.z;
    int bm = blockIdx.y;
    int bn = blockIdx.x;

    const int8_t* Ag = (which ? g_pq : g_zq) + (size_t)(bm * BM) * DIM;
    const int8_t* Bg = g_cq + (size_t)(bn * BN) * DIM;
    const float* na = which ? g_np : g_nz;
    const float* rsa = which ? g_rsp : g_rsz;
    __half* T = which ? g_tp : g_tz;

    // loaders: 512 threads, 2 tiles, 128 rows each, 2 threads per row (128 B each)
    int ltile = tid >> 8;         // 0 = A, 1 = B
    int local = tid & 255;
    int lrow = local >> 1;        // 0..127
    int lhalf = local & 1;        // which 128-byte half of the 256B row
    const int8_t* gsrc = (ltile ? Bg : Ag) + (size_t)lrow * DIM + lhalf * 128;
    uint32_t sdst = (ltile ? sB : sA) + lrow * ROWB + lhalf * 128;

    #pragma unroll
    for (int c2 = 0; c2 < 8; c2++)
        CP_ASYNC16(sdst + c2 * 16, gsrc + c2 * 16);
    CP_COMMIT();

    int acc[2][4][4];
    #pragma unroll
    for (int i = 0; i < 2; i++)
        #pragma unroll
        for (int j = 0; j < 4; j++)
            #pragma unroll
            for (int k = 0; k < 4; k++)
                acc[i][j][k] = 0;

    uint32_t aBase = sA + (wm * 32 + (lane & 15)) * ROWB + (lane >> 4) * 16;
    uint32_t bBase = sB + (wn * 32 + (lane & 7) + ((lane >> 4) << 3)) * ROWB
                     + ((lane >> 3) & 1) * 16;

    CP_WAIT(0);
    __syncthreads();          // the only mainloop barrier

    #pragma unroll
    for (int k32 = 0; k32 < 8; k32++) {
        uint32_t a[2][4], b[2][4];
        #pragma unroll
        for (int mt = 0; mt < 2; mt++)
            LDSM_X4(a[mt][0], a[mt][1], a[mt][2], a[mt][3],
                    aBase + mt * (16 * ROWB) + k32 * 32);
        #pragma unroll
        for (int j = 0; j < 2; j++)
            LDSM_X4(b[j][0], b[j][1], b[j][2], b[j][3],
                    bBase + j * (16 * ROWB) + k32 * 32);
        #pragma unroll
        for (int mt = 0; mt < 2; mt++)
            #pragma unroll
            for (int nt = 0; nt < 4; nt++)
                mma_s8(acc[mt][nt], a[mt], &b[nt >> 1][(nt & 1) * 2]);
    }

    // ---------------- epilogue (no smem, no syncs) ----------------
    float nc0v[4], nc1v[4], rb0[4], rb1[4];
    #pragma unroll
    for (int nt = 0; nt < 4; nt++) {
        int c = bn * BN + wn * 32 + nt * 8 + 2 * q;
        nc0v[nt] = g_nc[c];
        nc1v[nt] = g_nc[c + 1];
        rb0[nt] = g_rsc[c];
        rb1[nt] = g_rsc[c + 1];
    }

    float es0[4], es1[4];
    #pragma unroll
    for (int nt = 0; nt < 4; nt++) { es0[nt] = 0.f; es1[nt] = 0.f; }

    #pragma unroll
    for (int mt = 0; mt < 2; mt++) {
        int r = bm * BM + wm * 32 + mt * 16 + gr;
        float na0 = na[r], na1 = na[r + 8];
        float ra0 = rsa[r], ra1 = rsa[r + 8];
        #pragma unroll
        for (int nt = 0; nt < 4; nt++) {
            int c = bn * BN + wn * 32 + nt * 8 + 2 * q;
            float g00 = (float)acc[mt][nt][0] * (ra0 * rb0[nt]);
            float g01 = (float)acc[mt][nt][1] * (ra0 * rb1[nt]);
            float g10 = (float)acc[mt][nt][2] * (ra1 * rb0[nt]);
            float g11 = (float)acc[mt][nt][3] * (ra1 * rb1[nt]);
            float t00 = distf(na0 + nc0v[nt] - 2.0f * g00);
            float t01 = distf(na0 + nc1v[nt] - 2.0f * g01);
            float t10 = distf(na1 + nc0v[nt] - 2.0f * g10);
            float t11 = distf(na1 + nc1v[nt] - 2.0f * g11);
            *(__half2*)&T[(size_t)r * KC + c]       = __floats2half2_rn(t00, t01);
            *(__half2*)&T[(size_t)(r + 8) * KC + c] = __floats2half2_rn(t10, t11);
            es0[nt] += __expf(t00) + __expf(t10);
            es1[nt] += __expf(t01) + __expf(t11);
        }
    }

    // reduce across the 8 lanes (gr) sharing each column, then 4 lanes emit
    // global fire-and-forget atomics to distinct addresses.
    #pragma unroll
    for (int o = 4; o <= 16; o <<= 1) {
        #pragma unroll
        for (int nt = 0; nt < 4; nt++) {
            es0[nt] += __shfl_xor_sync(0xffffffffu, es0[nt], o);
            es1[nt] += __shfl_xor_sync(0xffffffffu, es1[nt], o);
        }
    }
    if (lane < 4) {   // gr == 0, q == lane
        int csbase = (which * 2 + (bm >> 7)) * KC + bn * BN + wn * 32 + 2 * lane;
        #pragma unroll
        for (int nt = 0; nt < 4; nt++) {
            atomicAdd(&g_cs[csbase + nt * 8], es0[nt]);
            atomicAdd(&g_cs[csbase + nt * 8 + 1], es1[nt]);
        }
    }
}

// ---------------- tail kernels ----------------
__global__ void logcs_kernel() {
    int i = blockIdx.x * blockDim.x + threadIdx.x;
    if (i < 4 * KC) g_lcs[i] = logf(g_cs[i]);
}

__global__ __launch_bounds__(256) void final_kernel() {
    __shared__ float sm[32];
    int b = blockIdx.x;
    int t = threadIdx.x;
    int lane = t & 31;
    int wid = t >> 5;
    int k0 = t * 4;

    uint2 rz1 = *(const uint2*)(g_tz + (size_t)b * KC + k0);
    uint2 rz2 = *(const uint2*)(g_tz + (size_t)(b + B_HALF) * KC + k0);
    uint2 rp1 = *(const uint2*)(g_tp + (size_t)b * KC + k0);
    uint2 rp2 = *(const uint2*)(g_tp + (size_t)(b + B_HALF) * KC + k0);
    float4 l1 = *(const float4*)(g_lcs + k0);
    float4 l2 = *(const float4*)(g_lcs + KC + k0);
    float4 l3 = *(const float4*)(g_lcs + 2 * KC + k0);
    float4 l4 = *(const float4*)(g_lcs + 3 * KC + k0);

    float tz1[4], tz2[4], tp1[4], tp2[4];
    {
        float2 a, bb;
        a = __half22float2(*(__half2*)&rz1.x); bb = __half22float2(*(__half2*)&rz1.y);
        tz1[0] = a.x; tz1[1] = a.y; tz1[2] = bb.x; tz1[3] = bb.y;
        a = __half22float2(*(__half2*)&rz2.x); bb = __half22float2(*(__half2*)&rz2.y);
        tz2[0] = a.x; tz2[1] = a.y; tz2[2] = bb.x; tz2[3] = bb.y;
        a = __half22float2(*(__half2*)&rp1.x); bb = __half22float2(*(__half2*)&rp1.y);
        tp1[0] = a.x; tp1[1] = a.y; tp1[2] = bb.x; tp1[3] = bb.y;
        a = __half22float2(*(__half2*)&rp2.x); bb = __half22float2(*(__half2*)&rp2.y);
        tp2[0] = a.x; tp2[1] = a.y; tp2[2] = bb.x; tp2[3] = bb.y;
    }
    float lc1[4] = {l1.x, l1.y, l1.z, l1.w};
    float lc2[4] = {l2.x, l2.y, l2.z, l2.w};
    float lc3[4] = {l3.x, l3.y, l3.z, l3.w};
    float lc4[4] = {l4.x, l4.y, l4.z, l4.w};

    float az1[4], az2[4], lp[4];
    float az1s = 0.f, az2s = 0.f, ap1s = 0.f, ap2s = 0.f;
    #pragma unroll
    for (int j = 0; j < 4; j++) {
        float u1 = tz1[j] - lc1[j];
        float u2 = tz2[j] - lc2[j];
        float v1 = tp1[j] - lc3[j];
        float v2 = tp2[j] - lc4[j];
        az1[j] = __expf(u1); az1s += az1[j];
        az2[j] = __expf(u2); az2s += az2[j];
        ap1s += __expf(v1);
        ap2s += __expf(v2);
        lp[j] = v1 + v2;
    }

    #pragma unroll
    for (int o = 16; o > 0; o >>= 1) {
        az1s += __shfl_xor_sync(0xffffffffu, az1s, o);
        az2s += __shfl_xor_sync(0xffffffffu, az2s, o);
        ap1s += __shfl_xor_sync(0xffffffffu, ap1s, o);
        ap2s += __shfl_xor_sync(0xffffffffu, ap2s, o);
    }
    if (lane == 0) {
        sm[wid * 4 + 0] = az1s; sm[wid * 4 + 1] = az2s;
        sm[wid * 4 + 2] = ap1s; sm[wid * 4 + 3] = ap2s;
    }
    __syncthreads();
    if (t < 32) {
        float v = sm[t];
        v += __shfl_xor_sync(0xffffffffu, v, 4);
        v += __shfl_xor_sync(0xffffffffu, v, 8);
        v += __shfl_xor_sync(0xffffffffu, v, 16);
        if (t < 4) sm[t] = v;
    }
    __syncthreads();
    float rz1s = sm[0], rz2s = sm[1], rp1s = sm[2], rp2s = sm[3];

    float lr = logf(rp1s) + logf(rp2s);
    float irz1 = 1.0f / rz1s;
    float irz2 = 1.0f / rz2s;
    float dot = 0.f;
    #pragma unroll
    for (int j = 0; j < 4; j++)
        dot += (az1[j] * irz1 + az2[j] * irz2) * (lp[j] - lr);

    #pragma unroll
    for (int o = 16; o > 0; o >>= 1)
        dot += __shfl_xor_sync(0xffffffffu, dot, o);
    if (lane == 0) sm[8 + wid] = dot;
    __syncthreads();
    if (t < 32) {
        float v = (t < 8) ? sm[8 + t] : 0.f;
        v += __shfl_xor_sync(0xffffffffu, v, 1);
        v += __shfl_xor_sync(0xffffffffu, v, 2);
        v += __shfl_xor_sync(0xffffffffu, v, 4);
        if (t == 0)
            atomicAdd(&g_loss, -(double)v / (4.0 * (double)B_HALF));
    }
}

__global__ void finalize_kernel(float* out) {
    out[0] = (float)g_loss;
}

// ---------------- launch ----------------
extern "C" void kernel_launch(void* const* d_in, const int* in_sizes, int n_in,
                              void* d_out, int out_size) {
    const float* z = (const float*)d_in[0];
    const float* p = (const float*)d_in[1];
    const float* c = (const float*)d_in[2];
    float* out = (float*)d_out;

    cudaFuncSetAttribute(gemm_dist_imma, cudaFuncAttributeMaxDynamicSharedMemorySize, SMEM_TOTAL);

    normalize_kernel<<<(2 * TWO_B + KC) / 8, 256>>>(z, p, c);
    dim3 ggrid(KC / BN, TWO_B / BM, 2);
    gemm_dist_imma<<<ggrid, 512, SMEM_TOTAL>>>();
    logcs_kernel<<<16, 256>>>();
    final_kernel<<<B_HALF, 256>>>();
    finalize_kernel<<<1, 1>>>(out);
}